// round 7
// baseline (speedup 1.0000x reference)
#include <cuda_runtime.h>

#define TX 128
#define TY_C 16            // rows per chunk
#define NCHUNK 8
#define STRIP (TY_C * NCHUNK)   // 128 rows per block
#define NTHREADS 256
#define SMW 136            // mosaick tile width: halo 4 each side
#define SMQ 34             // SMW/4
#define SMH_C (TY_C + 4)   // 20
#define SDW 68
#define SDH_C (TY_C + 2)   // 18
#define NF4 3              // ceil(20*34 / 256)
#define EPS 1e-8f

// ---- prefetch next chunk into registers (edge-clamped) ----
__device__ __forceinline__ void prefetch_regs(
    const float* __restrict__ mb, int bx0, int gy0, int H, int W,
    int tid, bool xint, float4* r)
{
    #pragma unroll
    for (int s = 0; s < NF4; ++s) {
        int idx = tid + s * NTHREADS;
        if (idx < SMH_C * SMQ) {
            int row = idx / SMQ;
            int q   = idx - row * SMQ;
            int gy  = min(max(gy0 - 2 + row, 0), H - 1);
            const float* rp = mb + (size_t)gy * W;
            int gx0 = bx0 - 4 + 4 * q;
            if (xint) {
                r[s] = *reinterpret_cast<const float4*>(&rp[gx0]);
            } else {
                float4 v;
                v.x = rp[min(max(gx0,     0), W - 1)];
                v.y = rp[min(max(gx0 + 1, 0), W - 1)];
                v.z = rp[min(max(gx0 + 2, 0), W - 1)];
                v.w = rp[min(max(gx0 + 3, 0), W - 1)];
                r[s] = v;
            }
        }
    }
}

__device__ __forceinline__ void commit_regs(
    float tile[SMH_C][SMW], int tid, const float4* r)
{
    #pragma unroll
    for (int s = 0; s < NF4; ++s) {
        int idx = tid + s * NTHREADS;
        if (idx < SMH_C * SMQ) {
            int row = idx / SMQ;
            int q   = idx - row * SMQ;
            *reinterpret_cast<float4*>(&tile[row][4 * q]) = r[s];
        }
    }
}

// Fused learnable demosaick, y-pipelined over 8 chunks of 16 rows.
//  sm column i <-> global x = bx0 + i - 4; sm row r <-> y = gy0 + r - 2
//  sd row j <-> y = gy0 + j - 1; sd[j][k] = (m - g_interp) at i = 2k + (1-(y&1))
__global__ __launch_bounds__(NTHREADS) void demosaick_kernel(
    const float* __restrict__ m,
    const float* __restrict__ gfilt,
    const float* __restrict__ grad_filt,
    float* __restrict__ out,
    int H, int W)
{
    __shared__ __align__(16) float sm[SMH_C][SMW];
    __shared__ __align__(16) float sd[SDH_C][SDW];

    const int bx0 = blockIdx.x * TX;
    const int by0 = blockIdx.y * STRIP;
    const int b   = blockIdx.z;
    const float* __restrict__ mb = m + (size_t)b * H * W;
    const int tid = threadIdx.x;
    const bool xint = (bx0 >= 4) && (bx0 + SMW - 4 <= W);

    const float gf0 = gfilt[0], gf1 = gfilt[1], gf2 = gfilt[2];
    const float r0  = grad_filt[0], r1 = grad_filt[1], r2 = grad_filt[2];

    const size_t img = (size_t)H * W;
    float* __restrict__ outr = out + (size_t)(b * 3 + 0) * img;
    float* __restrict__ outg = out + (size_t)(b * 3 + 1) * img;
    float* __restrict__ outb = out + (size_t)(b * 3 + 2) * img;

    const int c   = tid & 63;          // pair column
    const int grp = tid >> 6;          // 4 groups
    const int x0  = bx0 + 2 * c;
    const int cb  = 2 * c + 4;

    float4 pf[NF4];
    prefetch_regs(mb, bx0, by0, H, W, tid, xint, pf);
    commit_regs(sm, tid, pf);
    __syncthreads();

    for (int k = 0; k < NCHUNK; ++k) {
        const int gy0 = by0 + k * TY_C;

        // issue next chunk's loads now; consumed after this chunk's compute
        if (k + 1 < NCHUNK)
            prefetch_regs(mb, bx0, gy0 + TY_C, H, W, tid, xint, pf);

        // ---- diff fill (row-pair interleaved: conflict-free sm reads) ----
        {
            const int NP = SDH_C * 66;     // 18 rows * 66 sites
            for (int idx = tid; idx < NP; idx += NTHREADS) {
                int p  = idx >> 1;
                int l  = idx & 1;
                int jp = p / 66;
                int kk = p - jp * 66 + 1;   // k in [1,66]
                int j  = 2 * jp + l;
                int y  = gy0 - 1 + j;
                int pr = 1 - (y & 1);
                int i  = 2 * kk + pr;

                float cc = sm[j + 1][i];
                float xl = sm[j + 1][i - 1];
                float xr = sm[j + 1][i + 1];
                float yu = sm[j][i];
                float yd = sm[j + 2][i];

                float gh = gf0 * xl + gf1 * cc + gf2 * xr;
                float gv = gf0 * yu + gf1 * cc + gf2 * yd;
                float dx = r0 * xl + r1 * cc + r2 * xr;
                float dy = r0 * yu + r1 * cc + r2 * yd;

                float adx = fabsf(dx), ady = fabsf(dy);
                float w   = __fdividef(ady, adx + ady + EPS);
                sd[j][kk] = cc - (w * gh + (1.0f - w) * gv);
            }
        }
        __syncthreads();

        // ---- chroma + output: vertical row pair per iteration ----
        #pragma unroll
        for (int rr = 0; rr < 2; ++rr) {
            const int ty = 2 * (grp + 4 * rr);   // 0,2,...,14
            const int y  = gy0 + ty;             // even row
            const size_t o = (size_t)y * W + x0;

            const bool fast = (y > 0) & (y + 1 < H - 1) & (x0 > 0) & (x0 < W - 2);
            if (fast) {
                float2 m2t = *reinterpret_cast<const float2*>(&sm[ty + 2][cb]);
                float2 m2b = *reinterpret_cast<const float2*>(&sm[ty + 3][cb]);

                float du0 = sd[ty][c + 2];
                float du2 = sd[ty][c + 3];
                float dLo = sd[ty + 1][c + 1];
                float dCo = sd[ty + 1][c + 2];
                float dd0 = sd[ty + 2][c + 2];
                float dd2 = sd[ty + 2][c + 3];
                float dda = sd[ty + 3][c + 1];
                float ddb = sd[ty + 3][c + 2];

                float2 Gt, Rt, Bt;
                Gt.x = m2t.x;
                Gt.y = m2t.y - dCo;
                Rt.x = Gt.x + 0.5f * (dLo + dCo);
                Rt.y = m2t.y;
                Bt.x = Gt.x + 0.5f  * (du0 + dd0);
                Bt.y = Gt.y + 0.25f * (du0 + du2 + dd0 + dd2);

                float2 Gb, Rb, Bb;
                Gb.x = m2b.x - dd0;
                Gb.y = m2b.y;
                Bb.x = m2b.x;
                Bb.y = Gb.y + 0.5f * (dd0 + dd2);
                Rb.x = Gb.x + 0.25f * (dLo + dCo + dda + ddb);
                Rb.y = Gb.y + 0.5f  * (dCo + ddb);

                *reinterpret_cast<float2*>(&outr[o])     = Rt;
                *reinterpret_cast<float2*>(&outg[o])     = Gt;
                *reinterpret_cast<float2*>(&outb[o])     = Bt;
                *reinterpret_cast<float2*>(&outr[o + W]) = Rb;
                *reinterpret_cast<float2*>(&outg[o + W]) = Gb;
                *reinterpret_cast<float2*>(&outb[o + W]) = Bb;
            } else {
                #pragma unroll
                for (int ry = 0; ry < 2; ++ry) {
                    const int yr = y + ry;
                    const size_t orow = o + (size_t)ry * W;
                    #pragma unroll
                    for (int kk = 0; kk < 2; ++kk) {
                        int x  = x0 + kk;
                        int ii = cb + kk;
                        float mv = sm[ty + 2 + ry][ii];
                        bool isg = ((x & 1) == (yr & 1));
                        int pro  = 1 - (yr & 1);
                        float g  = isg ? mv : mv - sd[ty + 1 + ry][(ii - pro) >> 1];

                        float nr = 0.f, dr = 0.f, nb = 0.f, db = 0.f;
                        #pragma unroll
                        for (int dyy = -1; dyy <= 1; ++dyy) {
                            #pragma unroll
                            for (int dxx = -1; dxx <= 1; ++dxx) {
                                int yy = yr + dyy, xx = x + dxx;
                                if (yy < 0 || yy >= H || xx < 0 || xx >= W) continue;
                                bool isr = ((yy & 1) == 0) & ((xx & 1) == 1);
                                bool isb = ((yy & 1) == 1) & ((xx & 1) == 0);
                                if (isr | isb) {
                                    float kw = 0.25f * (float)((2 - abs(dyy)) * (2 - abs(dxx)));
                                    int prr  = 1 - (yy & 1);
                                    float d  = sd[ty + 1 + ry + dyy][(ii + dxx - prr) >> 1];
                                    if (isr) { nr += kw * d; dr += kw; }
                                    else     { nb += kw * d; db += kw; }
                                }
                            }
                        }
                        outr[orow + kk] = g + nr / (dr + EPS);
                        outg[orow + kk] = g;
                        outb[orow + kk] = g + nb / (db + EPS);
                    }
                }
            }
        }
        __syncthreads();              // all reads of sm/sd done

        if (k + 1 < NCHUNK) {
            commit_regs(sm, tid, pf);
            __syncthreads();
        }
    }
}

extern "C" void kernel_launch(void* const* d_in, const int* in_sizes, int n_in,
                              void* d_out, int out_size)
{
    const float* m         = (const float*)d_in[0];
    const float* gfilt     = (const float*)d_in[1];
    const float* grad_filt = (const float*)d_in[2];
    float* out             = (float*)d_out;

    const int H = 1024, W = 1024;
    const int B = in_sizes[0] / (H * W);

    dim3 block(NTHREADS);
    dim3 grid(W / TX, H / STRIP, B);
    demosaick_kernel<<<grid, block>>>(m, gfilt, grad_filt, out, H, W);
}

// round 8
// speedup vs baseline: 1.1731x; 1.1731x over previous
#include <cuda_runtime.h>

#define EPS 1e-8f
#define STRIPH 32
#define NTHREADS 256
#define FULLMASK 0xffffffffu

// green-interp diff at a non-green site: returns m - g_interp
__device__ __forceinline__ float gdiff(float c, float xl, float xr, float yu, float yd,
                                       float gf0, float gf1, float gf2,
                                       float r0, float r1, float r2)
{
    float gh = gf0*xl + gf1*c + gf2*xr;
    float gv = gf0*yu + gf1*c + gf2*yd;
    float dx = r0*xl + r1*c + r2*xr;
    float dy = r0*yu + r1*c + r2*yd;
    float adx = fabsf(dx), ady = fabsf(dy);
    float w = __fdividef(ady, adx + ady + EPS);
    return c - (w*gh + (1.0f - w)*gv);
}

// Warp-register streaming demosaick. Each warp: 64-px-wide x 32-row strip.
// Lane l owns pixels (x0+2l, x0+2l+1). Even rows are G R, odd rows B G.
// Diff pipeline (scalars/lane): one non-green site per lane per row.
// Halo diffs at x0-1 (even rows, lane 0) / x0+64 (odd rows, lane 31).
__global__ __launch_bounds__(NTHREADS) void demosaick_kernel(
    const float* __restrict__ m,
    const float* __restrict__ gfilt,
    const float* __restrict__ grad_filt,
    float* __restrict__ out,
    int H, int W)
{
    const int lane = threadIdx.x & 31;
    const int wrp  = threadIdx.x >> 5;

    const int xblocks = W / 512;            // x-blocks of 8 warps * 64 px
    const int nys     = H / STRIPH;
    const int xb = blockIdx.x % xblocks;
    const int ys = (blockIdx.x / xblocks) % nys;
    const int b  = blockIdx.x / (xblocks * nys);

    const int x0 = (xb * 8 + wrp) * 64;
    const int y0 = ys * STRIPH;

    const float* __restrict__ mb = m + (size_t)b * H * W;
    const size_t img = (size_t)H * W;
    float* __restrict__ outr = out + (size_t)(b*3+0)*img;
    float* __restrict__ outg = out + (size_t)(b*3+1)*img;
    float* __restrict__ outb = out + (size_t)(b*3+2)*img;

    const float gf0 = gfilt[0], gf1 = gfilt[1], gf2 = gfilt[2];
    const float r0 = grad_filt[0], r1 = grad_filt[1], r2 = grad_filt[2];

    const bool xl0 = (x0 == 0);
    const bool xr0 = (x0 + 64 == W);
    const int offm = x0 + 2*lane;
    int offq = offm;                        // halo span (real data on lanes 0 / 31)
    if (lane == 0)  offq = max(x0 - 2, 0);
    if (lane == 31) offq = min(x0 + 64, W - 2);
    const bool rsel = (lane == 31);

    auto ld = [&](int y, int off) -> float2 {
        y = min(max(y, 0), H - 1);
        return *reinterpret_cast<const float2*>(mb + (size_t)y * W + off);
    };

    // ---------------- prologue: d[y0-1], d[y0], halo diffs ----------------
    float2 t0 = ld(y0-2, offm), t1 = ld(y0-1, offm), t2 = ld(y0, offm), t3 = ld(y0+1, offm);
    float2 q0 = ld(y0-2, offq), q1 = ld(y0-1, offq), q2 = ld(y0, offq), q3 = ld(y0+1, offq);

    float xlv = __shfl_up_sync(FULLMASK, t1.y, 1);
    if (lane == 0) xlv = xl0 ? t1.x : q1.y;
    float dOdd_prev = gdiff(t1.x, xlv, t1.y, t0.x, t2.x, gf0,gf1,gf2,r0,r1,r2);  // d[y0-1] (odd row)

    float xrv = __shfl_down_sync(FULLMASK, t2.x, 1);
    if (lane == 31) xrv = xr0 ? t2.y : q2.x;
    float dEv_cur = gdiff(t2.y, t2.x, xrv, t1.y, t3.y, gf0,gf1,gf2,r0,r1,r2);    // d[y0] (even row)

    float hL_cur, hR_prev;
    {
        // lane31: right halo diff at row y0-1 (odd); others: left halo diff at row y0 (even)
        float hc  = rsel ? q1.x : q2.y;
        float hxl = rsel ? t1.y : q2.x;
        float hxr = rsel ? q1.y : t2.x;
        float hyu = rsel ? q0.x : q1.y;
        float hyd = rsel ? q2.x : q3.y;
        float h = gdiff(hc,hxl,hxr,hyu,hyd, gf0,gf1,gf2,r0,r1,r2);
        hL_cur = h; hR_prev = h;
    }

    float2 mA = t2, mB = t3;
    float2 mC = ld(y0+2, offm), mD = ld(y0+3, offm);
    float2 qA = q2, qB = q3;
    float2 qC = ld(y0+2, offq), qD = ld(y0+3, offq);

    // ---------------- main march: 2 rows per iteration ----------------
    #pragma unroll 4
    for (int y = y0; y < y0 + STRIPH; y += 2) {
        // d[y+1] (odd row): site .x
        float a = __shfl_up_sync(FULLMASK, mB.y, 1);
        if (lane == 0) a = xl0 ? mB.x : qB.y;
        float dOdd_cur = gdiff(mB.x, a, mB.y, mA.x, mC.x, gf0,gf1,gf2,r0,r1,r2);

        // d[y+2] (even row): site .y
        float bb = __shfl_down_sync(FULLMASK, mC.x, 1);
        if (lane == 31) bb = xr0 ? mC.y : qC.x;
        float dEv_next = gdiff(mC.y, mC.x, bb, mB.y, mD.y, gf0,gf1,gf2,r0,r1,r2);

        // combined halo diff: lane31 -> right @ row y+1 (odd), lane0 -> left @ row y+2 (even)
        float hc  = rsel ? qB.x : qC.y;
        float hxl = rsel ? mB.y : qC.x;
        float hxr = rsel ? qB.y : mC.x;
        float hyu = rsel ? qA.x : qB.y;
        float hyd = rsel ? qC.x : qD.y;
        float h = gdiff(hc,hxl,hxr,hyu,hyd, gf0,gf1,gf2,r0,r1,r2);
        float hL_next = h;     // valid on lane 0
        float hR_cur  = h;     // valid on lane 31

        // prefetch next window rows while chroma computes
        float2 nmC = ld(y+4, offm), nmD = ld(y+5, offm);
        float2 nqC = ld(y+4, offq), nqD = ld(y+5, offq);

        const size_t o = (size_t)y * W + offm;

        // ---- chroma even row y (G R) ----
        {
            float dCo = dEv_cur;
            float dLo = __shfl_up_sync(FULLMASK, dEv_cur, 1);
            if (lane == 0) dLo = xl0 ? dCo : hL_cur;
            float du0 = dOdd_prev, dd0 = dOdd_cur;
            float du2 = __shfl_down_sync(FULLMASK, dOdd_prev, 1);
            float dd2 = __shfl_down_sync(FULLMASK, dOdd_cur, 1);
            if (lane == 31) { du2 = xr0 ? du0 : hR_prev; dd2 = xr0 ? dd0 : hR_cur; }
            if (y == 0) { du0 = dd0; du2 = dd2; }      // zero-pad mirror at top

            float2 G, R, Bv;
            G.x = mA.x;               G.y = mA.y - dCo;
            R.x = G.x + 0.5f*(dLo + dCo);   R.y = mA.y;
            Bv.x = G.x + 0.5f*(du0 + dd0);
            Bv.y = G.y + 0.25f*(du0 + du2 + dd0 + dd2);

            __stcs(reinterpret_cast<float2*>(outr + o), R);
            __stcs(reinterpret_cast<float2*>(outg + o), G);
            __stcs(reinterpret_cast<float2*>(outb + o), Bv);
        }

        // ---- chroma odd row y+1 (B G) ----
        {
            float d0 = dOdd_cur;
            float d2 = __shfl_down_sync(FULLMASK, dOdd_cur, 1);
            if (lane == 31) d2 = xr0 ? d0 : hR_cur;
            float dub = dEv_cur, ddb = dEv_next;
            float dua = __shfl_up_sync(FULLMASK, dEv_cur, 1);
            float dda = __shfl_up_sync(FULLMASK, dEv_next, 1);
            if (lane == 0) { dua = xl0 ? dub : hL_cur; dda = xl0 ? ddb : hL_next; }
            if (y + 1 == H - 1) { dda = dua; ddb = dub; }   // zero-pad mirror at bottom

            float2 G, R, Bv;
            G.x = mB.x - d0;          G.y = mB.y;
            Bv.x = mB.x;              Bv.y = G.y + 0.5f*(d0 + d2);
            R.x = G.x + 0.25f*(dua + dub + dda + ddb);
            R.y = G.y + 0.5f*(dub + ddb);

            __stcs(reinterpret_cast<float2*>(outr + o + W), R);
            __stcs(reinterpret_cast<float2*>(outg + o + W), G);
            __stcs(reinterpret_cast<float2*>(outb + o + W), Bv);
        }

        // ---- shift pipeline ----
        mA = mC; mB = mD; mC = nmC; mD = nmD;
        qA = qC; qB = qD; qC = nqC; qD = nqD;
        dOdd_prev = dOdd_cur; dEv_cur = dEv_next;
        hL_cur = hL_next; hR_prev = hR_cur;
    }
}

extern "C" void kernel_launch(void* const* d_in, const int* in_sizes, int n_in,
                              void* d_out, int out_size)
{
    const float* m         = (const float*)d_in[0];
    const float* gfilt     = (const float*)d_in[1];
    const float* grad_filt = (const float*)d_in[2];
    float* out             = (float*)d_out;

    const int H = 1024, W = 1024;
    const int B = in_sizes[0] / (H * W);

    const int xblocks = W / 512;             // 8 warps * 64 px
    const int nys     = H / STRIPH;
    dim3 grid(xblocks * nys * B);
    demosaick_kernel<<<grid, NTHREADS>>>(m, gfilt, grad_filt, out, H, W);
}

// round 9
// speedup vs baseline: 1.2309x; 1.0493x over previous
#include <cuda_runtime.h>

#define EPS 1e-8f
#define STRIPH 32
#define NTHREADS 256
#define FULLMASK 0xffffffffu

// green-interp diff at a non-green site: returns m - g_interp
__device__ __forceinline__ float gdiff(float c, float xl, float xr, float yu, float yd,
                                       float gf0, float gf1, float gf2,
                                       float r0, float r1, float r2)
{
    float gh = gf0*xl + gf1*c + gf2*xr;
    float gv = gf0*yu + gf1*c + gf2*yd;
    float dx = r0*xl + r1*c + r2*xr;
    float dy = r0*yu + r1*c + r2*yd;
    float adx = fabsf(dx), ady = fabsf(dy);
    float w = __fdividef(ady, adx + ady + EPS);
    return c - (w*gh + (1.0f - w)*gv);
}

// Warp-register streaming demosaick. Each warp: 64-px-wide x 32-row strip.
// Lane l owns pixels (x0+2l, x0+2l+1). Even rows are G R, odd rows B G.
// Halo loads (q) predicated to lanes 0 / 31 only.
__global__ __launch_bounds__(NTHREADS) void demosaick_kernel(
    const float* __restrict__ m,
    const float* __restrict__ gfilt,
    const float* __restrict__ grad_filt,
    float* __restrict__ out,
    int H, int W)
{
    const int lane = threadIdx.x & 31;
    const int wrp  = threadIdx.x >> 5;

    const int xblocks = W / 512;            // x-blocks of 8 warps * 64 px
    const int nys     = H / STRIPH;
    const int xb = blockIdx.x % xblocks;
    const int ys = (blockIdx.x / xblocks) % nys;
    const int b  = blockIdx.x / (xblocks * nys);

    const int x0 = (xb * 8 + wrp) * 64;
    const int y0 = ys * STRIPH;

    const float* __restrict__ mb = m + (size_t)b * H * W;
    const size_t img = (size_t)H * W;
    float* __restrict__ outr = out + (size_t)(b*3+0)*img;
    float* __restrict__ outg = out + (size_t)(b*3+1)*img;
    float* __restrict__ outb = out + (size_t)(b*3+2)*img;

    const float gf0 = gfilt[0], gf1 = gfilt[1], gf2 = gfilt[2];
    const float r0 = grad_filt[0], r1 = grad_filt[1], r2 = grad_filt[2];

    const bool xl0 = (x0 == 0);
    const bool xr0 = (x0 + 64 == W);
    const int offm = x0 + 2*lane;
    const bool rsel  = (lane == 31);
    const bool haloL = (lane == 0);
    int offq = offm;
    if (haloL) offq = max(x0 - 2, 0);
    if (rsel)  offq = min(x0 + 64, W - 2);
    const bool qact = haloL | rsel;

    auto ld = [&](int y, int off) -> float2 {
        y = min(max(y, 0), H - 1);
        return *reinterpret_cast<const float2*>(mb + (size_t)y * W + off);
    };
    auto ldq = [&](int y) -> float2 {
        if (qact) return ld(y, offq);
        return make_float2(0.f, 0.f);
    };

    // ---------------- prologue: d[y0-1], d[y0], halo diffs ----------------
    float2 t0 = ld(y0-2, offm), t1 = ld(y0-1, offm), t2 = ld(y0, offm), t3 = ld(y0+1, offm);
    float2 q0 = ldq(y0-2), q1 = ldq(y0-1), q2 = ldq(y0), q3 = ldq(y0+1);

    float xlv = __shfl_up_sync(FULLMASK, t1.y, 1);
    if (haloL) xlv = xl0 ? t1.x : q1.y;
    float dOdd_prev = gdiff(t1.x, xlv, t1.y, t0.x, t2.x, gf0,gf1,gf2,r0,r1,r2);  // d[y0-1]

    float xrv = __shfl_down_sync(FULLMASK, t2.x, 1);
    if (rsel) xrv = xr0 ? t2.y : q2.x;
    float dEv_cur = gdiff(t2.y, t2.x, xrv, t1.y, t3.y, gf0,gf1,gf2,r0,r1,r2);    // d[y0]

    float hL_cur, hR_prev;
    {
        // lane31: right halo diff @ row y0-1 (odd); lane0: left halo diff @ row y0 (even)
        float hc  = rsel ? q1.x : q2.y;
        float hxl = rsel ? t1.y : q2.x;
        float hxr = rsel ? q1.y : t2.x;
        float hyu = rsel ? q0.x : q1.y;
        float hyd = rsel ? q2.x : q3.y;
        float h = gdiff(hc,hxl,hxr,hyu,hyd, gf0,gf1,gf2,r0,r1,r2);
        hL_cur = h; hR_prev = h;
    }

    float2 mA = t2, mB = t3;
    float2 mC = ld(y0+2, offm), mD = ld(y0+3, offm);
    float2 qA = q2, qB = q3;
    float2 qC = ldq(y0+2), qD = ldq(y0+3);

    // ---------------- main march: 2 rows per iteration ----------------
    #pragma unroll 4
    for (int y = y0; y < y0 + STRIPH; y += 2) {
        // d[y+1] (odd row): site .x
        float a = __shfl_up_sync(FULLMASK, mB.y, 1);
        if (haloL) a = xl0 ? mB.x : qB.y;
        float dOdd_cur = gdiff(mB.x, a, mB.y, mA.x, mC.x, gf0,gf1,gf2,r0,r1,r2);

        // d[y+2] (even row): site .y
        float bb = __shfl_down_sync(FULLMASK, mC.x, 1);
        if (rsel) bb = xr0 ? mC.y : qC.x;
        float dEv_next = gdiff(mC.y, mC.x, bb, mB.y, mD.y, gf0,gf1,gf2,r0,r1,r2);

        // combined halo diff: lane31 -> right @ y+1 (odd), lane0 -> left @ y+2 (even)
        float hc  = rsel ? qB.x : qC.y;
        float hxl = rsel ? mB.y : qC.x;
        float hxr = rsel ? qB.y : mC.x;
        float hyu = rsel ? qA.x : qB.y;
        float hyd = rsel ? qC.x : qD.y;
        float h = gdiff(hc,hxl,hxr,hyu,hyd, gf0,gf1,gf2,r0,r1,r2);
        float hL_next = h;     // valid on lane 0
        float hR_cur  = h;     // valid on lane 31

        // prefetch next window rows while chroma computes
        float2 nmC = ld(y+4, offm), nmD = ld(y+5, offm);
        float2 nqC = ldq(y+4),      nqD = ldq(y+5);

        const size_t o = (size_t)y * W + offm;

        // ---- chroma even row y (G R) ----
        {
            float dCo = dEv_cur;
            float dLo = __shfl_up_sync(FULLMASK, dEv_cur, 1);
            if (haloL) dLo = xl0 ? dCo : hL_cur;
            float du0 = dOdd_prev, dd0 = dOdd_cur;
            float du2 = __shfl_down_sync(FULLMASK, dOdd_prev, 1);
            float dd2 = __shfl_down_sync(FULLMASK, dOdd_cur, 1);
            if (rsel) { du2 = xr0 ? du0 : hR_prev; dd2 = xr0 ? dd0 : hR_cur; }
            if (y == 0) { du0 = dd0; du2 = dd2; }      // zero-pad mirror at top

            float2 G, R, Bv;
            G.x = mA.x;               G.y = mA.y - dCo;
            R.x = G.x + 0.5f*(dLo + dCo);   R.y = mA.y;
            Bv.x = G.x + 0.5f*(du0 + dd0);
            Bv.y = G.y + 0.25f*(du0 + du2 + dd0 + dd2);

            __stcs(reinterpret_cast<float2*>(outr + o), R);
            __stcs(reinterpret_cast<float2*>(outg + o), G);
            __stcs(reinterpret_cast<float2*>(outb + o), Bv);
        }

        // ---- chroma odd row y+1 (B G) ----
        {
            float d0 = dOdd_cur;
            float d2 = __shfl_down_sync(FULLMASK, dOdd_cur, 1);
            if (rsel) d2 = xr0 ? d0 : hR_cur;
            float dub = dEv_cur, ddb = dEv_next;
            float dua = __shfl_up_sync(FULLMASK, dEv_cur, 1);
            float dda = __shfl_up_sync(FULLMASK, dEv_next, 1);
            if (haloL) { dua = xl0 ? dub : hL_cur; dda = xl0 ? ddb : hL_next; }
            if (y + 1 == H - 1) { dda = dua; ddb = dub; }   // zero-pad mirror at bottom

            float2 G, R, Bv;
            G.x = mB.x - d0;          G.y = mB.y;
            Bv.x = mB.x;              Bv.y = G.y + 0.5f*(d0 + d2);
            R.x = G.x + 0.25f*(dua + dub + dda + ddb);
            R.y = G.y + 0.5f*(dub + ddb);

            __stcs(reinterpret_cast<float2*>(outr + o + W), R);
            __stcs(reinterpret_cast<float2*>(outg + o + W), G);
            __stcs(reinterpret_cast<float2*>(outb + o + W), Bv);
        }

        // ---- shift pipeline ----
        mA = mC; mB = mD; mC = nmC; mD = nmD;
        qA = qC; qB = qD; qC = nqC; qD = nqD;
        dOdd_prev = dOdd_cur; dEv_cur = dEv_next;
        hL_cur = hL_next; hR_prev = hR_cur;
    }
}

extern "C" void kernel_launch(void* const* d_in, const int* in_sizes, int n_in,
                              void* d_out, int out_size)
{
    const float* m         = (const float*)d_in[0];
    const float* gfilt     = (const float*)d_in[1];
    const float* grad_filt = (const float*)d_in[2];
    float* out             = (float*)d_out;

    const int H = 1024, W = 1024;
    const int B = in_sizes[0] / (H * W);

    const int xblocks = W / 512;             // 8 warps * 64 px
    const int nys     = H / STRIPH;
    dim3 grid(xblocks * nys * B);
    demosaick_kernel<<<grid, NTHREADS>>>(m, gfilt, grad_filt, out, H, W);
}